// round 3
// baseline (speedup 1.0000x reference)
#include <cuda_runtime.h>

// OpticalFlowLK on 2048x2048 fp32 images.
// Fused single kernel: gradients -> products -> 3x3 box sums -> 2x2 solve.

#define IMH 2048
#define IMW 2048
#define TX 32
#define TY 32
#define NTHREADS 256

__global__ __launch_bounds__(NTHREADS)
void lk_flow_kernel(const float* __restrict__ prev,
                    const float* __restrict__ next,
                    float* __restrict__ out) {
    // Image staging region: rows y0-1 .. y0+TY+1 (35), cols x0-1 .. x0+TX+1 (35)
    __shared__ float sp[35][36];
    __shared__ float sn[35][36];
    // Product maps over rows y0-1..y0+TY (34), cols x0-1..x0+TX (34)
    __shared__ float pxx[34][34];
    __shared__ float pyy[34][34];
    __shared__ float pxy[34][34];
    __shared__ float pxt[34][34];
    __shared__ float pyt[34][34];

    const int x0 = blockIdx.x * TX;
    const int y0 = blockIdx.y * TY;
    const int tid = threadIdx.y * 32 + threadIdx.x;

    // ---- Stage images with reflect-after clamp (index H maps to H-2). ----
    // Rows/cols < 0 or > H only ever feed zeroed products, so any valid clamp works there.
    for (int idx = tid; idx < 35 * 35; idx += NTHREADS) {
        int r = idx / 35, c = idx % 35;
        int gy = y0 - 1 + r;
        int gx = x0 - 1 + c;
        int cy = gy;
        if (cy < 0) cy = 0;
        else if (cy == IMH) cy = IMH - 2;
        else if (cy > IMH) cy = 0;
        int cx = gx;
        if (cx < 0) cx = 0;
        else if (cx == IMW) cx = IMW - 2;
        else if (cx > IMW) cx = 0;
        const int off = cy * IMW + cx;
        sp[r][c] = prev[off];
        sn[r][c] = next[off];
    }
    __syncthreads();

    // ---- Gradients + per-pixel products (zero outside the image: box3 zero-pad). ----
    for (int idx = tid; idx < 34 * 34; idx += NTHREADS) {
        int r = idx / 34, c = idx % 34;
        int gy = y0 - 1 + r;
        int gx = x0 - 1 + c;
        float xx = 0.f, yy = 0.f, xy = 0.f, xt = 0.f, yt = 0.f;
        if (gy >= 0 && gy < IMH && gx >= 0 && gx < IMW) {
            float a0 = sp[r][c],     b0 = sp[r][c + 1];
            float c0 = sp[r + 1][c], d0 = sp[r + 1][c + 1];
            float a1 = sn[r][c],     b1 = sn[r][c + 1];
            float c1 = sn[r + 1][c], d1 = sn[r + 1][c + 1];
            float gxp = -a0 + b0 - c0 + d0;
            float gyp = -a0 - b0 + c0 + d0;
            float gsp =  a0 + b0 + c0 + d0;
            float gxn = -a1 + b1 - c1 + d1;
            float gyn = -a1 - b1 + c1 + d1;
            float gsn =  a1 + b1 + c1 + d1;
            float rx = 0.5f * (gxp + gxn);
            float ry = 0.5f * (gyp + gyn);
            float rt = 0.5f * (gsn - gsp);
            xx = rx * rx;
            yy = ry * ry;
            xy = rx * ry;
            xt = rt * rx;
            yt = rt * ry;
        }
        pxx[r][c] = xx;
        pyy[r][c] = yy;
        pxy[r][c] = xy;
        pxt[r][c] = xt;
        pyt[r][c] = yt;
    }
    __syncthreads();

    // ---- 3x3 box sums + 2x2 solve. Each thread handles 4 output rows. ----
    const int tx = threadIdx.x;
    #pragma unroll
    for (int k = 0; k < TY / 8; k++) {
        const int ty = threadIdx.y + k * 8;
        float Sxx = 0.f, Syy = 0.f, Sxy = 0.f, Sxt = 0.f, Syt = 0.f;
        #pragma unroll
        for (int dy = 0; dy < 3; dy++) {
            #pragma unroll
            for (int dx = 0; dx < 3; dx++) {
                Sxx += pxx[ty + dy][tx + dx];
                Syy += pyy[ty + dy][tx + dx];
                Sxy += pxy[ty + dy][tx + dx];
                Sxt += pxt[ty + dy][tx + dx];
                Syt += pyt[ty + dy][tx + dx];
            }
        }
        float det = Sxx * Syy - Sxy * Sxy;
        float u = 0.f, v = 0.f;
        if (det != 0.f) {
            u = (Syy * Sxt - Sxy * Syt) / det;
            v = (Sxx * Syt - Sxy * Sxt) / det;
        }
        const int gy = y0 + ty;
        const int gx = x0 + tx;
        if (gy == 0 || gx == 0) { u = 0.f; v = 0.f; }
        out[gy * IMW + gx] = u;
        out[IMH * IMW + gy * IMW + gx] = v;
    }
}

extern "C" void kernel_launch(void* const* d_in, const int* in_sizes, int n_in,
                              void* d_out, int out_size) {
    const float* prev = (const float*)d_in[0];
    const float* next = (const float*)d_in[1];
    float* out = (float*)d_out;
    dim3 block(32, 8, 1);
    dim3 grid(IMW / TX, IMH / TY, 1);
    lk_flow_kernel<<<grid, block>>>(prev, next, out);
}

// round 4
// speedup vs baseline: 1.8245x; 1.8245x over previous
#include <cuda_runtime.h>

// OpticalFlowLK 2048x2048 fp32, fully register-resident:
// one thread per column, rolling 32-row strip, warp shuffles for horizontal
// neighbor exchange. No shared memory.

#define IMH 2048
#define IMW 2048
#define STRIP 32
#define WPB 4                 // warps per block
#define OCW 29                // useful output columns per warp (lanes 1..29)
#define NGROUPS ((IMW + OCW - 1) / OCW)   // 71

struct P5 { float xx, yy, xy, xt, yt; };

__device__ __forceinline__ int rowclamp(int r) {
    // reflect-after pad: row IMH maps to IMH-2; out-of-range rows only feed
    // zeroed products, any safe index works there.
    if (r < 0) return 0;
    if (r == IMH) return IMH - 2;
    if (r > IMH) return 0;
    return r;
}

// Compute horizontal 3-sums of the 5 product channels for one product row.
// (pPt,pPb) = prev image rows pr, pr+1 at this lane's column; (pNt,pNb) same for next.
__device__ __forceinline__ P5 row_H(float pPt, float pPb, float pNt, float pNb,
                                    bool pvalid) {
    const unsigned FULL = 0xffffffffu;
    float sP = pPt + pPb, dP = pPb - pPt;
    float sN = pNt + pNb, dN = pNb - pNt;
    float S = 0.5f * (sP + sN);   // rx = S(c+1) - S(c)
    float D = 0.5f * (dP + dN);   // ry = D(c) + D(c+1)
    float T = 0.5f * (sN - sP);   // rt = T(c) + T(c+1)
    float S1 = __shfl_down_sync(FULL, S, 1);
    float D1 = __shfl_down_sync(FULL, D, 1);
    float T1 = __shfl_down_sync(FULL, T, 1);
    float rx = S1 - S;
    float ry = D + D1;
    float rt = T + T1;
    float xx = rx * rx, yy = ry * ry, xy = rx * ry, xt = rt * rx, yt = rt * ry;
    if (!pvalid) { xx = 0.f; yy = 0.f; xy = 0.f; xt = 0.f; yt = 0.f; }
    P5 h;
    h.xx = xx + __shfl_up_sync(FULL, xx, 1) + __shfl_down_sync(FULL, xx, 1);
    h.yy = yy + __shfl_up_sync(FULL, yy, 1) + __shfl_down_sync(FULL, yy, 1);
    h.xy = xy + __shfl_up_sync(FULL, xy, 1) + __shfl_down_sync(FULL, xy, 1);
    h.xt = xt + __shfl_up_sync(FULL, xt, 1) + __shfl_down_sync(FULL, xt, 1);
    h.yt = yt + __shfl_up_sync(FULL, yt, 1) + __shfl_down_sync(FULL, yt, 1);
    return h;
}

__global__ __launch_bounds__(32 * WPB)
void lk_flow_kernel(const float* __restrict__ prev,
                    const float* __restrict__ next,
                    float* __restrict__ out) {
    const int lane = threadIdx.x;
    const int g = blockIdx.x * WPB + threadIdx.y;   // column group, one per warp
    if (g >= NGROUPS) return;

    const int ob = g * OCW;            // first output column of this group
    const int ic = ob - 1 + lane;      // this lane's image/product column
    int icc = ic;
    if (icc < 0) icc = 0;
    else if (icc == IMW) icc = IMW - 2;   // reflect-after
    else if (icc > IMW) icc = 0;
    const bool colvalid = (lane < 31) && (ic >= 0) && (ic < IMW);

    const int r0 = blockIdx.y * STRIP;
    const float* P = prev + icc;
    const float* N = next + icc;

    // ---- Prologue: H for product rows r0-1 and r0. (r0 <= 2016, so rows up
    // to r0+2 are in-range; only r0-1 can be negative.)
    float t0P = P[(size_t)rowclamp(r0 - 1) * IMW];
    float t0N = N[(size_t)rowclamp(r0 - 1) * IMW];
    float t1P = P[(size_t)r0 * IMW];
    float t1N = N[(size_t)r0 * IMW];
    P5 h0 = row_H(t0P, t1P, t0N, t1N, colvalid && (r0 > 0));

    float t2P = P[(size_t)(r0 + 1) * IMW];
    float t2N = N[(size_t)(r0 + 1) * IMW];
    P5 h1 = row_H(t1P, t2P, t1N, t2N, colvalid);

    // Rolling image rows for the loop: A = row r+1, B = row r+2 (at iter r=r0).
    float AP = t2P, AN = t2N;
    float BP = P[(size_t)(r0 + 2) * IMW];
    float BN = N[(size_t)(r0 + 2) * IMW];

    const bool storelane = (lane >= 1) && (lane <= 29) && (ic < IMW);

    #pragma unroll 4
    for (int r = r0; r < r0 + STRIP; ++r) {
        // Prefetch row r+3 (next iteration's B) early.
        const size_t rc = (size_t)rowclamp(r + 3) * IMW;
        float CP = P[rc];
        float CN = N[rc];

        // H for product row r+1 (uses image rows r+1, r+2).
        P5 h2 = row_H(AP, BP, AN, BN, colvalid && (r + 1 < IMH));

        float Sxx = h0.xx + h1.xx + h2.xx;
        float Syy = h0.yy + h1.yy + h2.yy;
        float Sxy = h0.xy + h1.xy + h2.xy;
        float Sxt = h0.xt + h1.xt + h2.xt;
        float Syt = h0.yt + h1.yt + h2.yt;

        float det = Sxx * Syy - Sxy * Sxy;
        float u = 0.f, v = 0.f;
        if (det != 0.f) {
            float inv = 1.0f / det;
            u = (Syy * Sxt - Sxy * Syt) * inv;
            v = (Sxx * Syt - Sxy * Sxt) * inv;
        }
        if (r == 0 || ic == 0) { u = 0.f; v = 0.f; }

        if (storelane) {
            out[(size_t)r * IMW + ic] = u;
            out[(size_t)IMH * IMW + (size_t)r * IMW + ic] = v;
        }

        // Roll.
        h0 = h1; h1 = h2;
        AP = BP; AN = BN;
        BP = CP; BN = CN;
    }
}

extern "C" void kernel_launch(void* const* d_in, const int* in_sizes, int n_in,
                              void* d_out, int out_size) {
    const float* prev = (const float*)d_in[0];
    const float* next = (const float*)d_in[1];
    float* out = (float*)d_out;
    dim3 block(32, WPB, 1);
    dim3 grid((NGROUPS + WPB - 1) / WPB, IMH / STRIP, 1);
    lk_flow_kernel<<<grid, block>>>(prev, next, out);
}

// round 5
// speedup vs baseline: 1.8634x; 1.0213x over previous
#include <cuda_runtime.h>

// OpticalFlowLK 2048x2048 fp32. Register-rolling vertical scan, float2 per
// lane (2 columns), warp shuffles for horizontal exchange. No shared memory.

#define IMH 2048
#define IMW 2048
#define STRIP 16
#define WPB 4
#define WOUT 60                 // output columns per warp
#define NGROUPS 35              // ceil(2048 / 60)
#define FULL 0xffffffffu

struct P5 { float2 xx, yy, xy, xt, yt; };

__device__ __forceinline__ int rowclamp(int r) {
    if (r < 0) return 0;
    if (r == IMH) return IMH - 2;   // reflect-after
    if (r > IMH) return 0;
    return r;
}

__device__ __forceinline__ void loadrow(const float* __restrict__ P,
                                        const float* __restrict__ N,
                                        size_t rb, int c0, int cc0, int cc1,
                                        bool vec, float2& p, float2& n) {
    if (vec) {
        p = *reinterpret_cast<const float2*>(P + rb + c0);
        n = *reinterpret_cast<const float2*>(N + rb + c0);
    } else {
        p.x = P[rb + cc0]; p.y = P[rb + cc1];
        n.x = N[rb + cc0]; n.y = N[rb + cc1];
    }
}

// Products for one product row, from image rows (top, bottom) of both images.
__device__ __forceinline__ P5 prodrow(float2 tP, float2 bP, float2 tN, float2 bN,
                                      bool v0, bool v1) {
    float sP0 = tP.x + bP.x, sP1 = tP.y + bP.y;
    float dP0 = bP.x - tP.x, dP1 = bP.y - tP.y;
    float sN0 = tN.x + bN.x, sN1 = tN.y + bN.y;
    float dN0 = bN.x - tN.x, dN1 = bN.y - tN.y;
    float S0 = 0.5f * (sP0 + sN0), S1 = 0.5f * (sP1 + sN1);
    float D0 = 0.5f * (dP0 + dN0), D1 = 0.5f * (dP1 + dN1);
    float T0 = 0.5f * (sN0 - sP0), T1 = 0.5f * (sN1 - sP1);
    float Sn = __shfl_down_sync(FULL, S0, 1);
    float Dn = __shfl_down_sync(FULL, D0, 1);
    float Tn = __shfl_down_sync(FULL, T0, 1);
    float rx0 = S1 - S0, rx1 = Sn - S1;
    float ry0 = D0 + D1, ry1 = D1 + Dn;
    float rt0 = T0 + T1, rt1 = T1 + Tn;
    P5 q;
    q.xx.x = v0 ? rx0 * rx0 : 0.f;  q.xx.y = v1 ? rx1 * rx1 : 0.f;
    q.yy.x = v0 ? ry0 * ry0 : 0.f;  q.yy.y = v1 ? ry1 * ry1 : 0.f;
    q.xy.x = v0 ? rx0 * ry0 : 0.f;  q.xy.y = v1 ? rx1 * ry1 : 0.f;
    q.xt.x = v0 ? rt0 * rx0 : 0.f;  q.xt.y = v1 ? rt1 * rx1 : 0.f;
    q.yt.x = v0 ? rt0 * ry0 : 0.f;  q.yt.y = v1 ? rt1 * ry1 : 0.f;
    return q;
}

// Horizontal 3-sum of a vertical-sum channel: H(c) = V(c-1)+V(c)+V(c+1).
__device__ __forceinline__ float2 hbox(float2 V) {
    float pv = __shfl_up_sync(FULL, V.y, 1);
    float nv = __shfl_down_sync(FULL, V.x, 1);
    float2 h;
    h.x = pv + V.x + V.y;
    h.y = V.x + V.y + nv;
    return h;
}

__global__ __launch_bounds__(32 * WPB)
void lk_flow_kernel(const float* __restrict__ prev,
                    const float* __restrict__ next,
                    float* __restrict__ out) {
    const int lane = threadIdx.x;
    const int g = blockIdx.x * WPB + threadIdx.y;
    if (g >= NGROUPS) return;

    const int ob = g * WOUT;
    const int c0 = ob - 2 + 2 * lane;    // even -> float2 aligned
    const int c1 = c0 + 1;
    int cc0 = c0;
    if (cc0 < 0) cc0 = 0; else if (cc0 >= IMW) cc0 = (cc0 == IMW) ? IMW - 2 : 0;
    int cc1 = c1;
    if (cc1 < 0) cc1 = 0; else if (cc1 >= IMW) cc1 = (cc1 == IMW) ? IMW - 2 : 0;
    const bool vec = (c0 >= 0) && (c1 < IMW);
    const bool cv0 = (c0 >= 0) && (c0 < IMW);
    const bool cv1 = (c1 >= 0) && (c1 < IMW);

    const int r0 = blockIdx.y * STRIP;

    float2 i0p, i0n, i1p, i1n, i2p, i2n;
    loadrow(prev, next, (size_t)rowclamp(r0 - 1) * IMW, c0, cc0, cc1, vec, i0p, i0n);
    loadrow(prev, next, (size_t)r0 * IMW,               c0, cc0, cc1, vec, i1p, i1n);
    P5 qa = prodrow(i0p, i1p, i0n, i1n, cv0 && (r0 > 0), cv1 && (r0 > 0));

    loadrow(prev, next, (size_t)(r0 + 1) * IMW,         c0, cc0, cc1, vec, i2p, i2n);
    P5 qb = prodrow(i1p, i2p, i1n, i2n, cv0, cv1);

    float2 Ap = i2p, An = i2n, Bp, Bn;
    loadrow(prev, next, (size_t)(r0 + 2) * IMW,         c0, cc0, cc1, vec, Bp, Bn);

    const bool storelane = (lane >= 1) && (lane <= 30) && (c0 < IMW);
    float2* outU = reinterpret_cast<float2*>(out + (size_t)0);
    float2* outV = reinterpret_cast<float2*>(out + (size_t)IMH * IMW);

    #pragma unroll 4
    for (int r = r0; r < r0 + STRIP; ++r) {
        float2 Cp, Cn;
        loadrow(prev, next, (size_t)rowclamp(r + 3) * IMW, c0, cc0, cc1, vec, Cp, Cn);

        const bool rv = (r + 1 < IMH);
        P5 qc = prodrow(Ap, Bp, An, Bn, cv0 && rv, cv1 && rv);

        float2 Vxx, Vyy, Vxy, Vxt, Vyt;
        Vxx.x = qa.xx.x + qb.xx.x + qc.xx.x;  Vxx.y = qa.xx.y + qb.xx.y + qc.xx.y;
        Vyy.x = qa.yy.x + qb.yy.x + qc.yy.x;  Vyy.y = qa.yy.y + qb.yy.y + qc.yy.y;
        Vxy.x = qa.xy.x + qb.xy.x + qc.xy.x;  Vxy.y = qa.xy.y + qb.xy.y + qc.xy.y;
        Vxt.x = qa.xt.x + qb.xt.x + qc.xt.x;  Vxt.y = qa.xt.y + qb.xt.y + qc.xt.y;
        Vyt.x = qa.yt.x + qb.yt.x + qc.yt.x;  Vyt.y = qa.yt.y + qb.yt.y + qc.yt.y;

        float2 Sxx = hbox(Vxx);
        float2 Syy = hbox(Vyy);
        float2 Sxy = hbox(Vxy);
        float2 Sxt = hbox(Vxt);
        float2 Syt = hbox(Vyt);

        float det0 = Sxx.x * Syy.x - Sxy.x * Sxy.x;
        float det1 = Sxx.y * Syy.y - Sxy.y * Sxy.y;
        float u0 = 0.f, v0_ = 0.f, u1 = 0.f, v1_ = 0.f;
        if (det0 != 0.f) {
            float inv = 1.0f / det0;
            u0  = (Syy.x * Sxt.x - Sxy.x * Syt.x) * inv;
            v0_ = (Sxx.x * Syt.x - Sxy.x * Sxt.x) * inv;
        }
        if (det1 != 0.f) {
            float inv = 1.0f / det1;
            u1  = (Syy.y * Sxt.y - Sxy.y * Syt.y) * inv;
            v1_ = (Sxx.y * Syt.y - Sxy.y * Sxt.y) * inv;
        }
        if (r == 0) { u0 = u1 = v0_ = v1_ = 0.f; }
        if (c0 == 0) { u0 = 0.f; v0_ = 0.f; }   // col 0 stays zero (c1 is odd, never 0)

        if (storelane) {
            const size_t o = ((size_t)r * IMW + c0) >> 1;
            outU[o] = make_float2(u0, u1);
            outV[o] = make_float2(v0_, v1_);
        }

        qa = qb; qb = qc;
        Ap = Bp; An = Bn;
        Bp = Cp; Bn = Cn;
    }
}

extern "C" void kernel_launch(void* const* d_in, const int* in_sizes, int n_in,
                              void* d_out, int out_size) {
    const float* prev = (const float*)d_in[0];
    const float* next = (const float*)d_in[1];
    float* out = (float*)d_out;
    dim3 block(32, WPB, 1);
    dim3 grid((NGROUPS + WPB - 1) / WPB, IMH / STRIP, 1);
    lk_flow_kernel<<<grid, block>>>(prev, next, out);
}

// round 6
// speedup vs baseline: 2.1520x; 1.1548x over previous
#include <cuda_runtime.h>

// OpticalFlowLK 2048x2048 fp32. Register-rolling vertical scan, float2 per
// lane, warp shuffles for horizontal exchange. Interior blocks take a fully
// branchless fast path; boundary blocks take the general path.

#define IMH 2048
#define IMW 2048
#define ROW2 (IMW / 2)          // row stride in float2
#define STRIP 16
#define WPB 4
#define WOUT 60                 // output columns per warp
#define NGROUPS 35              // ceil(2048 / 60)
#define FULL 0xffffffffu

struct P5 { float2 xx, yy, xy, xt, yt; };

__device__ __forceinline__ int rowclamp(int r) {
    if (r < 0) return 0;
    if (r == IMH) return IMH - 2;   // reflect-after
    if (r > IMH) return 0;
    return r;
}

// ---------------- interior (branchless) helpers ----------------
// NOTE: 0.5 gradient factors dropped -> all tensor sums scale 4x uniformly;
// u, v and the det==0 set are invariant.

__device__ __forceinline__ P5 prodrow_i(float2 tP, float2 bP, float2 tN, float2 bN) {
    float sP0 = tP.x + bP.x, sP1 = tP.y + bP.y;
    float dP0 = bP.x - tP.x, dP1 = bP.y - tP.y;
    float sN0 = tN.x + bN.x, sN1 = tN.y + bN.y;
    float dN0 = bN.x - tN.x, dN1 = bN.y - tN.y;
    float S0 = sP0 + sN0, S1 = sP1 + sN1;
    float D0 = dP0 + dN0, D1 = dP1 + dN1;
    float T0 = sN0 - sP0, T1 = sN1 - sP1;
    float Sn = __shfl_down_sync(FULL, S0, 1);
    float Dn = __shfl_down_sync(FULL, D0, 1);
    float Tn = __shfl_down_sync(FULL, T0, 1);
    float rx0 = S1 - S0, rx1 = Sn - S1;
    float ry0 = D0 + D1, ry1 = D1 + Dn;
    float rt0 = T0 + T1, rt1 = T1 + Tn;
    P5 q;
    q.xx = make_float2(rx0 * rx0, rx1 * rx1);
    q.yy = make_float2(ry0 * ry0, ry1 * ry1);
    q.xy = make_float2(rx0 * ry0, rx1 * ry1);
    q.xt = make_float2(rt0 * rx0, rt1 * rx1);
    q.yt = make_float2(rt0 * ry0, rt1 * ry1);
    return q;
}

__device__ __forceinline__ P5 p5add(const P5& a, const P5& b) {
    P5 r;
    r.xx = make_float2(a.xx.x + b.xx.x, a.xx.y + b.xx.y);
    r.yy = make_float2(a.yy.x + b.yy.x, a.yy.y + b.yy.y);
    r.xy = make_float2(a.xy.x + b.xy.x, a.xy.y + b.xy.y);
    r.xt = make_float2(a.xt.x + b.xt.x, a.xt.y + b.xt.y);
    r.yt = make_float2(a.yt.x + b.yt.x, a.yt.y + b.yt.y);
    return r;
}

__device__ __forceinline__ float2 hbox(float2 V) {
    float pv = __shfl_up_sync(FULL, V.y, 1);
    float nv = __shfl_down_sync(FULL, V.x, 1);
    return make_float2(pv + V.x + V.y, V.x + V.y + nv);
}

// ---------------- edge helpers (general path, as validated) ----------------

__device__ __forceinline__ void loadrow(const float* __restrict__ P,
                                        const float* __restrict__ N,
                                        size_t rb, int c0, int cc0, int cc1,
                                        bool vec, float2& p, float2& n) {
    if (vec) {
        p = *reinterpret_cast<const float2*>(P + rb + c0);
        n = *reinterpret_cast<const float2*>(N + rb + c0);
    } else {
        p.x = P[rb + cc0]; p.y = P[rb + cc1];
        n.x = N[rb + cc0]; n.y = N[rb + cc1];
    }
}

__device__ __forceinline__ P5 prodrow_e(float2 tP, float2 bP, float2 tN, float2 bN,
                                        bool v0, bool v1) {
    float sP0 = tP.x + bP.x, sP1 = tP.y + bP.y;
    float dP0 = bP.x - tP.x, dP1 = bP.y - tP.y;
    float sN0 = tN.x + bN.x, sN1 = tN.y + bN.y;
    float dN0 = bN.x - tN.x, dN1 = bN.y - tN.y;
    float S0 = sP0 + sN0, S1 = sP1 + sN1;
    float D0 = dP0 + dN0, D1 = dP1 + dN1;
    float T0 = sN0 - sP0, T1 = sN1 - sP1;
    float Sn = __shfl_down_sync(FULL, S0, 1);
    float Dn = __shfl_down_sync(FULL, D0, 1);
    float Tn = __shfl_down_sync(FULL, T0, 1);
    float rx0 = S1 - S0, rx1 = Sn - S1;
    float ry0 = D0 + D1, ry1 = D1 + Dn;
    float rt0 = T0 + T1, rt1 = T1 + Tn;
    P5 q;
    q.xx.x = v0 ? rx0 * rx0 : 0.f;  q.xx.y = v1 ? rx1 * rx1 : 0.f;
    q.yy.x = v0 ? ry0 * ry0 : 0.f;  q.yy.y = v1 ? ry1 * ry1 : 0.f;
    q.xy.x = v0 ? rx0 * ry0 : 0.f;  q.xy.y = v1 ? rx1 * ry1 : 0.f;
    q.xt.x = v0 ? rt0 * rx0 : 0.f;  q.xt.y = v1 ? rt1 * rx1 : 0.f;
    q.yt.x = v0 ? rt0 * ry0 : 0.f;  q.yt.y = v1 ? rt1 * ry1 : 0.f;
    return q;
}

__global__ __launch_bounds__(32 * WPB)
void lk_flow_kernel(const float* __restrict__ prev,
                    const float* __restrict__ next,
                    float* __restrict__ out) {
    const int lane = threadIdx.x;
    const int g = blockIdx.x * WPB + threadIdx.y;
    if (g >= NGROUPS) return;

    const int ob = g * WOUT;
    const int r0 = blockIdx.y * STRIP;
    const bool storelane = (lane >= 1) && (lane <= 30);

    const bool interior = (g >= 1) && (g <= 33) &&
                          (blockIdx.y >= 1) && (blockIdx.y <= 126);

    if (interior) {
        // ---------------- FAST PATH ----------------
        const int cidx = ((ob - 2) >> 1) + lane;     // float2 column index
        const float2* P2 = reinterpret_cast<const float2*>(prev)
                           + (size_t)(r0 - 1) * ROW2 + cidx;
        const float2* N2 = reinterpret_cast<const float2*>(next)
                           + (size_t)(r0 - 1) * ROW2 + cidx;

        float2 a0p = P2[0];        float2 a0n = N2[0];
        float2 a1p = P2[ROW2];     float2 a1n = N2[ROW2];
        float2 a2p = P2[2 * ROW2]; float2 a2n = N2[2 * ROW2];
        float2 Bp  = P2[3 * ROW2]; float2 Bn  = N2[3 * ROW2];

        P5 qm = prodrow_i(a0p, a1p, a0n, a1n);       // product row r0-1
        P5 q1 = prodrow_i(a1p, a2p, a1n, a2n);       // product row r0
        P5 s01 = p5add(qm, q1);                      // q(r-2)+q(r-1) rolling pair

        float2 Ap = a2p, An = a2n;
        const float2* Pf = P2 + 4 * ROW2;            // row r0+3
        const float2* Nf = N2 + 4 * ROW2;

        float2* outU = reinterpret_cast<float2*>(out);
        float2* outV = reinterpret_cast<float2*>(out + (size_t)IMH * IMW);
        size_t o = ((size_t)r0 * IMW + (ob - 2)) / 2 + lane;

        #pragma unroll 4
        for (int it = 0; it < STRIP; ++it) {
            float2 Cp = Pf[0], Cn = Nf[0];
            Pf += ROW2; Nf += ROW2;

            P5 q2 = prodrow_i(Ap, Bp, An, Bn);       // product row r+1

            float2 Vxx = make_float2(s01.xx.x + q2.xx.x, s01.xx.y + q2.xx.y);
            float2 Vyy = make_float2(s01.yy.x + q2.yy.x, s01.yy.y + q2.yy.y);
            float2 Vxy = make_float2(s01.xy.x + q2.xy.x, s01.xy.y + q2.xy.y);
            float2 Vxt = make_float2(s01.xt.x + q2.xt.x, s01.xt.y + q2.xt.y);
            float2 Vyt = make_float2(s01.yt.x + q2.yt.x, s01.yt.y + q2.yt.y);

            s01 = p5add(q1, q2);
            q1 = q2;

            float2 Sxx = hbox(Vxx);
            float2 Syy = hbox(Vyy);
            float2 Sxy = hbox(Vxy);
            float2 Sxt = hbox(Vxt);
            float2 Syt = hbox(Vyt);

            float det0 = Sxx.x * Syy.x - Sxy.x * Sxy.x;
            float det1 = Sxx.y * Syy.y - Sxy.y * Sxy.y;
            float u0 = 0.f, v0 = 0.f, u1 = 0.f, v1 = 0.f;
            if (det0 != 0.f) {
                float inv = __fdividef(1.0f, det0);
                u0 = (Syy.x * Sxt.x - Sxy.x * Syt.x) * inv;
                v0 = (Sxx.x * Syt.x - Sxy.x * Sxt.x) * inv;
            }
            if (det1 != 0.f) {
                float inv = __fdividef(1.0f, det1);
                u1 = (Syy.y * Sxt.y - Sxy.y * Syt.y) * inv;
                v1 = (Sxx.y * Syt.y - Sxy.y * Sxt.y) * inv;
            }

            if (storelane) {
                outU[o] = make_float2(u0, u1);
                outV[o] = make_float2(v0, v1);
            }
            o += ROW2;

            Ap = Bp; An = Bn;
            Bp = Cp; Bn = Cn;
        }
        return;
    }

    // ---------------- EDGE PATH (general, validated in R5) ----------------
    const int c0 = ob - 2 + 2 * lane;
    const int c1 = c0 + 1;
    int cc0 = c0;
    if (cc0 < 0) cc0 = 0; else if (cc0 >= IMW) cc0 = (cc0 == IMW) ? IMW - 2 : 0;
    int cc1 = c1;
    if (cc1 < 0) cc1 = 0; else if (cc1 >= IMW) cc1 = (cc1 == IMW) ? IMW - 2 : 0;
    const bool vec = (c0 >= 0) && (c1 < IMW);
    const bool cv0 = (c0 >= 0) && (c0 < IMW);
    const bool cv1 = (c1 >= 0) && (c1 < IMW);

    float2 i0p, i0n, i1p, i1n, i2p, i2n;
    loadrow(prev, next, (size_t)rowclamp(r0 - 1) * IMW, c0, cc0, cc1, vec, i0p, i0n);
    loadrow(prev, next, (size_t)r0 * IMW,               c0, cc0, cc1, vec, i1p, i1n);
    P5 qa = prodrow_e(i0p, i1p, i0n, i1n, cv0 && (r0 > 0), cv1 && (r0 > 0));

    loadrow(prev, next, (size_t)(r0 + 1) * IMW,         c0, cc0, cc1, vec, i2p, i2n);
    P5 qb = prodrow_e(i1p, i2p, i1n, i2n, cv0, cv1);

    float2 Ap = i2p, An = i2n, Bp, Bn;
    loadrow(prev, next, (size_t)(r0 + 2) * IMW,         c0, cc0, cc1, vec, Bp, Bn);

    const bool st = storelane && (c0 < IMW);
    float2* outU = reinterpret_cast<float2*>(out);
    float2* outV = reinterpret_cast<float2*>(out + (size_t)IMH * IMW);

    #pragma unroll 4
    for (int r = r0; r < r0 + STRIP; ++r) {
        float2 Cp, Cn;
        loadrow(prev, next, (size_t)rowclamp(r + 3) * IMW, c0, cc0, cc1, vec, Cp, Cn);

        const bool rv = (r + 1 < IMH);
        P5 qc = prodrow_e(Ap, Bp, An, Bn, cv0 && rv, cv1 && rv);

        float2 Vxx = make_float2(qa.xx.x + qb.xx.x + qc.xx.x, qa.xx.y + qb.xx.y + qc.xx.y);
        float2 Vyy = make_float2(qa.yy.x + qb.yy.x + qc.yy.x, qa.yy.y + qb.yy.y + qc.yy.y);
        float2 Vxy = make_float2(qa.xy.x + qb.xy.x + qc.xy.x, qa.xy.y + qb.xy.y + qc.xy.y);
        float2 Vxt = make_float2(qa.xt.x + qb.xt.x + qc.xt.x, qa.xt.y + qb.xt.y + qc.xt.y);
        float2 Vyt = make_float2(qa.yt.x + qb.yt.x + qc.yt.x, qa.yt.y + qb.yt.y + qc.yt.y);

        float2 Sxx = hbox(Vxx);
        float2 Syy = hbox(Vyy);
        float2 Sxy = hbox(Vxy);
        float2 Sxt = hbox(Vxt);
        float2 Syt = hbox(Vyt);

        float det0 = Sxx.x * Syy.x - Sxy.x * Sxy.x;
        float det1 = Sxx.y * Syy.y - Sxy.y * Sxy.y;
        float u0 = 0.f, v0 = 0.f, u1 = 0.f, v1 = 0.f;
        if (det0 != 0.f) {
            float inv = __fdividef(1.0f, det0);
            u0 = (Syy.x * Sxt.x - Sxy.x * Syt.x) * inv;
            v0 = (Sxx.x * Syt.x - Sxy.x * Sxt.x) * inv;
        }
        if (det1 != 0.f) {
            float inv = __fdividef(1.0f, det1);
            u1 = (Syy.y * Sxt.y - Sxy.y * Syt.y) * inv;
            v1 = (Sxx.y * Syt.y - Sxy.y * Sxt.y) * inv;
        }
        if (r == 0) { u0 = u1 = v0 = v1 = 0.f; }
        if (c0 == 0) { u0 = 0.f; v0 = 0.f; }

        if (st) {
            const size_t o = ((size_t)r * IMW + c0) >> 1;
            outU[o] = make_float2(u0, u1);
            outV[o] = make_float2(v0, v1);
        }

        qa = qb; qb = qc;
        Ap = Bp; An = Bn;
        Bp = Cp; Bn = Cn;
    }
}

extern "C" void kernel_launch(void* const* d_in, const int* in_sizes, int n_in,
                              void* d_out, int out_size) {
    const float* prev = (const float*)d_in[0];
    const float* next = (const float*)d_in[1];
    float* out = (float*)d_out;
    dim3 block(32, WPB, 1);
    dim3 grid((NGROUPS + WPB - 1) / WPB, IMH / STRIP, 1);
    lk_flow_kernel<<<grid, block>>>(prev, next, out);
}